// round 2
// baseline (speedup 1.0000x reference)
#include <cuda_runtime.h>
#include <cuda_bf16.h>
#include <math.h>

// Problem constants (Transformer_71957882077842)
#define LAYERS 8
#define HDIM   1024
#define KDIM   1024
#define IDIM   4096
#define VOCAB  32000
#define BATCH  2
#define SEQ    2048
#define MTOK   (BATCH * SEQ)   // 4096 tokens total

// ---------------- scratch (device globals; no cudaMalloc allowed) ----------
__device__ float g_x[(long)MTOK * HDIM];          // 16 MB  residual stream
__device__ float g_qkv[(long)MTOK * 3 * KDIM];    // 48 MB  fused qkv output
__device__ float g_scores[(long)BATCH * SEQ * SEQ]; // 32 MB attention scores
__device__ float g_o[(long)MTOK * KDIM];          // 16 MB  attn output
__device__ float g_h[(long)MTOK * IDIM];          // 64 MB  MLP hidden

// ---------------- embed gather --------------------------------------------
__global__ void embed_kernel(const int* __restrict__ tokens,
                             const float* __restrict__ emb,
                             float* __restrict__ x) {
    int i = blockIdx.x;                 // token index 0..MTOK-1
    int tok = tokens[i];
    const float4* src = (const float4*)(emb + (long)tok * HDIM);
    float4* dst = (float4*)(x + (long)i * HDIM);
    for (int c = threadIdx.x; c < HDIM / 4; c += blockDim.x) dst[c] = src[c];
}

// ---------------- causal softmax (in-place, with scale) --------------------
__global__ void softmax_causal(float* __restrict__ scores, float scale) {
    int row = blockIdx.x;               // b*SEQ + s
    int s = row & (SEQ - 1);
    float* p = scores + (long)row * SEQ;
    int tid = threadIdx.x;
    __shared__ float red[256];

    float m = -INFINITY;
    for (int t = tid; t <= s; t += blockDim.x) m = fmaxf(m, p[t] * scale);
    red[tid] = m; __syncthreads();
    for (int o = 128; o > 0; o >>= 1) {
        if (tid < o) red[tid] = fmaxf(red[tid], red[tid + o]);
        __syncthreads();
    }
    m = red[0]; __syncthreads();

    float sum = 0.f;
    for (int t = tid; t <= s; t += blockDim.x) {
        float e = __expf(p[t] * scale - m);
        p[t] = e;
        sum += e;
    }
    red[tid] = sum; __syncthreads();
    for (int o = 128; o > 0; o >>= 1) {
        if (tid < o) red[tid] += red[tid + o];
        __syncthreads();
    }
    float inv = 1.f / red[0];
    for (int t = tid; t <= s; t += blockDim.x) p[t] *= inv;
    for (int t = s + 1 + tid; t < SEQ; t += blockDim.x) p[t] = 0.f;
}

// ---------------- tiled SGEMM ----------------------------------------------
// C[M,N] = A[M,K] * B  (+ epilogue).  A row-major (lda), C row-major (ldc).
// TRANSB=false: B row-major [K,N] (ldb).  TRANSB=true: B row-major [N,K] (ldb),
// i.e. C = A * B^T (used for Q@K^T).
// EPI: 0 store, 1 +=C(residual in-place), 2 relu(.+bias), 3 +bias+C, 4 +bias
#define BM 128
#define BN 128
#define BK 8
#define TM 8
#define TN 8

template<int EPI, bool TRANSB>
__global__ __launch_bounds__(256)
void gemm_kernel(const float* __restrict__ A, const float* __restrict__ Bm,
                 float* __restrict__ C, const float* __restrict__ bias,
                 int Kd, int lda, int ldb, int ldc,
                 long bsA, long bsB, long bsC) {
    A  += (long)blockIdx.z * bsA;
    Bm += (long)blockIdx.z * bsB;
    C  += (long)blockIdx.z * bsC;

    __shared__ float As[BK][BM];
    __shared__ float Bs[BK][BN];

    const int tid = threadIdx.x;
    const int m0 = blockIdx.y * BM;
    const int n0 = blockIdx.x * BN;

    // transposed-load indices (A always; B when TRANSB)
    const int t_row = tid >> 1;            // 0..127
    const int t_k4  = (tid & 1) * 4;       // 0 or 4
    // direct-load indices (B when !TRANSB)
    const int b_row = tid >> 5;            // 0..7
    const int b_col = (tid & 31) * 4;      // 0..124

    const int tx = tid & 15, ty = tid >> 4;

    float acc[TM][TN];
    #pragma unroll
    for (int i = 0; i < TM; i++)
        #pragma unroll
        for (int j = 0; j < TN; j++) acc[i][j] = 0.f;

    for (int k0 = 0; k0 < Kd; k0 += BK) {
        float4 av = *(const float4*)(A + (long)(m0 + t_row) * lda + k0 + t_k4);
        As[t_k4 + 0][t_row] = av.x;
        As[t_k4 + 1][t_row] = av.y;
        As[t_k4 + 2][t_row] = av.z;
        As[t_k4 + 3][t_row] = av.w;
        if (TRANSB) {
            float4 bv = *(const float4*)(Bm + (long)(n0 + t_row) * ldb + k0 + t_k4);
            Bs[t_k4 + 0][t_row] = bv.x;
            Bs[t_k4 + 1][t_row] = bv.y;
            Bs[t_k4 + 2][t_row] = bv.z;
            Bs[t_k4 + 3][t_row] = bv.w;
        } else {
            float4 bv = *(const float4*)(Bm + (long)(k0 + b_row) * ldb + n0 + b_col);
            *(float4*)&Bs[b_row][b_col] = bv;
        }
        __syncthreads();

        #pragma unroll
        for (int k = 0; k < BK; k++) {
            float a[TM], b[TN];
            #pragma unroll
            for (int i = 0; i < TM; i++) a[i] = As[k][ty * TM + i];
            #pragma unroll
            for (int j = 0; j < TN; j++) b[j] = Bs[k][tx * TN + j];
            #pragma unroll
            for (int i = 0; i < TM; i++)
                #pragma unroll
                for (int j = 0; j < TN; j++) acc[i][j] = fmaf(a[i], b[j], acc[i][j]);
        }
        __syncthreads();
    }

    #pragma unroll
    for (int i = 0; i < TM; i++) {
        int m = m0 + ty * TM + i;
        #pragma unroll
        for (int j = 0; j < TN; j++) {
            int n = n0 + tx * TN + j;
            long idx = (long)m * ldc + n;
            float v = acc[i][j];
            if (EPI == 1) v += C[idx];
            if (EPI == 2) v = fmaxf(v + bias[n], 0.f);
            if (EPI == 3) v += bias[n] + C[idx];
            if (EPI == 4) v += bias[n];
            C[idx] = v;
        }
    }
}

// ---------------- host orchestration --------------------------------------
extern "C" void kernel_launch(void* const* d_in, const int* in_sizes, int n_in,
                              void* d_out, int out_size) {
    const int*   tokens    = (const int*)  d_in[0];
    const float* embedding = (const float*)d_in[1];
    const float* qkv_w     = (const float*)d_in[2];
    const float* o_w       = (const float*)d_in[3];
    const float* up_w      = (const float*)d_in[4];
    const float* up_b      = (const float*)d_in[5];
    const float* down_w    = (const float*)d_in[6];
    const float* down_b    = (const float*)d_in[7];
    const float* unemb_w   = (const float*)d_in[8];
    const float* unemb_b   = (const float*)d_in[9];
    float* logits = (float*)d_out;

    float *x, *qkvb, *scores, *o, *h;
    cudaGetSymbolAddress((void**)&x,      g_x);
    cudaGetSymbolAddress((void**)&qkvb,   g_qkv);
    cudaGetSymbolAddress((void**)&scores, g_scores);
    cudaGetSymbolAddress((void**)&o,      g_o);
    cudaGetSymbolAddress((void**)&h,      g_h);

    const float scale = 1.0f / sqrtf((float)KDIM);

    // 1. embed
    embed_kernel<<<MTOK, 256>>>(tokens, embedding, x);

    for (int l = 0; l < LAYERS; l++) {
        const float* wqkv = qkv_w  + (long)l * HDIM * 3 * KDIM;
        const float* wo   = o_w    + (long)l * KDIM * HDIM;
        const float* wu   = up_w   + (long)l * HDIM * IDIM;
        const float* bu   = up_b   + (long)l * IDIM;
        const float* wd   = down_w + (long)l * IDIM * HDIM;
        const float* bd   = down_b + (long)l * HDIM;

        // qkv: [4096,1024] x [1024,3072] -> g_qkv
        gemm_kernel<0, false><<<dim3(3 * KDIM / BN, MTOK / BM, 1), 256>>>(
            x, wqkv, qkvb, nullptr, HDIM, HDIM, 3 * KDIM, 3 * KDIM, 0, 0, 0);

        // scores = Q @ K^T per batch: [2048,1024] x [2048,1024]^T
        gemm_kernel<0, true><<<dim3(SEQ / BN, SEQ / BM, BATCH), 256>>>(
            qkvb,            /* Q at col 0   */
            qkvb + KDIM,     /* K at col KDIM */
            scores, nullptr, KDIM, 3 * KDIM, 3 * KDIM, SEQ,
            (long)SEQ * 3 * KDIM, (long)SEQ * 3 * KDIM, (long)SEQ * SEQ);

        // causal softmax (with scale folded in)
        softmax_causal<<<BATCH * SEQ, 256>>>(scores, scale);

        // o = attn @ V per batch: [2048,2048] x [2048,1024]
        gemm_kernel<0, false><<<dim3(KDIM / BN, SEQ / BM, BATCH), 256>>>(
            scores, qkvb + 2 * KDIM, o, nullptr, SEQ, SEQ, 3 * KDIM, KDIM,
            (long)SEQ * SEQ, (long)SEQ * 3 * KDIM, (long)SEQ * KDIM);

        // x += o @ Wo : [4096,1024] x [1024,1024]
        gemm_kernel<1, false><<<dim3(HDIM / BN, MTOK / BM, 1), 256>>>(
            o, wo, x, nullptr, KDIM, KDIM, HDIM, HDIM, 0, 0, 0);

        // h = relu(x @ Wu + bu) : [4096,1024] x [1024,4096]
        gemm_kernel<2, false><<<dim3(IDIM / BN, MTOK / BM, 1), 256>>>(
            x, wu, h, bu, HDIM, HDIM, IDIM, IDIM, 0, 0, 0);

        // x += h @ Wd + bd : [4096,4096] x [4096,1024]
        gemm_kernel<3, false><<<dim3(HDIM / BN, MTOK / BM, 1), 256>>>(
            h, wd, x, bd, IDIM, IDIM, HDIM, HDIM, 0, 0, 0);
    }

    // logits = x @ Wun + b : [4096,1024] x [1024,32000]
    gemm_kernel<4, false><<<dim3(VOCAB / BN, MTOK / BM, 1), 256>>>(
        x, unemb_w, logits, unemb_b, HDIM, HDIM, VOCAB, VOCAB, 0, 0, 0);
}

// round 4
// speedup vs baseline: 2.5041x; 2.5041x over previous
#include <cuda_runtime.h>
#include <cuda_bf16.h>
#include <math.h>
#include <stdint.h>

#define LAYERS 8
#define HDIM   1024
#define KDIM   1024
#define IDIM   4096
#define VOCAB  32000
#define BATCH  2
#define SEQ    2048
#define MTOK   (BATCH * SEQ)

typedef __nv_bfloat16 bf16;
typedef __nv_bfloat162 bf162;

// ---------------- scratch (device globals) ----------------
__device__ float g_x[(long)MTOK * HDIM];
__device__ float g_qkv[(long)MTOK * 3 * KDIM];
__device__ float g_scores[(long)BATCH * SEQ * SEQ];
__device__ bf16 g_xh[(long)MTOK * HDIM],      g_xl[(long)MTOK * HDIM];
__device__ bf16 g_qkvh[(long)MTOK * 3 * KDIM], g_qkvl[(long)MTOK * 3 * KDIM];
__device__ bf16 g_sh[(long)BATCH * SEQ * SEQ], g_sl[(long)BATCH * SEQ * SEQ];
__device__ bf16 g_vTh[(long)BATCH * KDIM * SEQ], g_vTl[(long)BATCH * KDIM * SEQ];
__device__ bf16 g_oh[(long)MTOK * KDIM],      g_ol[(long)MTOK * KDIM];
__device__ bf16 g_hh[(long)MTOK * IDIM],      g_hl[(long)MTOK * IDIM];
// transposed weights [N,K] bf16 hi/lo
__device__ bf16 g_qkvTh[(long)LAYERS * 3 * KDIM * HDIM], g_qkvTl[(long)LAYERS * 3 * KDIM * HDIM];
__device__ bf16 g_oTh[(long)LAYERS * HDIM * KDIM],       g_oTl[(long)LAYERS * HDIM * KDIM];
__device__ bf16 g_upTh[(long)LAYERS * IDIM * HDIM],      g_upTl[(long)LAYERS * IDIM * HDIM];
__device__ bf16 g_dnTh[(long)LAYERS * HDIM * IDIM],      g_dnTl[(long)LAYERS * HDIM * IDIM];
__device__ bf16 g_unTh[(long)VOCAB * HDIM],              g_unTl[(long)VOCAB * HDIM];

// ---------------- helpers ----------------
__device__ __forceinline__ uint32_t smem_u32(const void* p) {
    uint32_t a;
    asm("{ .reg .u64 t; cvta.to.shared.u64 t, %1; cvt.u32.u64 %0, t; }" : "=r"(a) : "l"(p));
    return a;
}
__device__ __forceinline__ void split1(float v, bf16& h, bf16& l) {
    h = __float2bfloat16_rn(v);
    l = __float2bfloat16_rn(v - __bfloat162float(h));
}

#define CP_ASYNC16(dst, src) \
    asm volatile("cp.async.cg.shared.global [%0], [%1], 16;" :: "r"(dst), "l"(src) : "memory")
#define CP_COMMIT() asm volatile("cp.async.commit_group;" ::: "memory")
#define CP_WAIT1()  asm volatile("cp.async.wait_group 1;" ::: "memory")

#define LDSM_X4(r, a)                                                        \
    asm volatile("ldmatrix.sync.aligned.m8n8.x4.shared.b16 {%0,%1,%2,%3}, [%4];" \
        : "=r"((r)[0]), "=r"((r)[1]), "=r"((r)[2]), "=r"((r)[3]) : "r"(a))

__device__ __forceinline__ void mma_bf16(float* c, const uint32_t* a,
                                         uint32_t b0, uint32_t b1) {
    asm volatile(
        "mma.sync.aligned.m16n8k16.row.col.f32.bf16.bf16.f32 "
        "{%0,%1,%2,%3}, {%4,%5,%6,%7}, {%8,%9}, {%0,%1,%2,%3};"
        : "+f"(c[0]), "+f"(c[1]), "+f"(c[2]), "+f"(c[3])
        : "r"(a[0]), "r"(a[1]), "r"(a[2]), "r"(a[3]), "r"(b0), "r"(b1));
}

// ---------------- embed (+split) ----------------
__global__ void embed_split(const int* __restrict__ tokens, const float* __restrict__ emb,
                            float* __restrict__ x, bf16* __restrict__ xh, bf16* __restrict__ xl) {
    int i = blockIdx.x;
    int tok = tokens[i];
    const float4* src = (const float4*)(emb + (long)tok * HDIM);
    float4* dst = (float4*)(x + (long)i * HDIM);
    for (int c = threadIdx.x; c < HDIM / 4; c += blockDim.x) {
        float4 v = src[c];
        dst[c] = v;
        bf16 h0, l0, h1, l1, h2, l2, h3, l3;
        split1(v.x, h0, l0); split1(v.y, h1, l1);
        split1(v.z, h2, l2); split1(v.w, h3, l3);
        long base = (long)i * HDIM + c * 4;
        bf162 a; a.x = h0; a.y = h1;
        bf162 b; b.x = h2; b.y = h3;
        *(bf162*)(xh + base) = a; *(bf162*)(xh + base + 2) = b;
        a.x = l0; a.y = l1; b.x = l2; b.y = l3;
        *(bf162*)(xl + base) = a; *(bf162*)(xl + base + 2) = b;
    }
}

// ---------------- transpose + split ----------------
// dst[(c0+j)*R + r0+x] = split(src[(r0+i)*lds + c0+x])
__global__ void transpose_split(const float* __restrict__ src,
                                bf16* __restrict__ dh, bf16* __restrict__ dl,
                                int R, int lds, long sbatch, long dbatch) {
    __shared__ float t[32][33];
    src += (long)blockIdx.z * sbatch;
    dh  += (long)blockIdx.z * dbatch;
    dl  += (long)blockIdx.z * dbatch;
    int c0 = blockIdx.x << 5, r0 = blockIdx.y << 5;
    int x = threadIdx.x, y = threadIdx.y;
    #pragma unroll
    for (int i = y; i < 32; i += 8)
        t[i][x] = src[(long)(r0 + i) * lds + c0 + x];
    __syncthreads();
    #pragma unroll
    for (int j = y; j < 32; j += 8) {
        float v = t[x][j];
        bf16 h, l; split1(v, h, l);
        long idx = (long)(c0 + j) * R + r0 + x;
        dh[idx] = h; dl[idx] = l;
    }
}

// ---------------- causal softmax -> split bf16 ----------------
__global__ void softmax_split(float* __restrict__ sc, bf16* __restrict__ sh,
                              bf16* __restrict__ sl, float scale) {
    int row = blockIdx.x;
    int s = row & (SEQ - 1);
    float* p = sc + (long)row * SEQ;
    bf16* ph = sh + (long)row * SEQ;
    bf16* pl = sl + (long)row * SEQ;
    int tid = threadIdx.x;
    __shared__ float red[256];

    float m = -INFINITY;
    for (int t = tid; t <= s; t += blockDim.x) m = fmaxf(m, p[t] * scale);
    red[tid] = m; __syncthreads();
    for (int o = 128; o > 0; o >>= 1) {
        if (tid < o) red[tid] = fmaxf(red[tid], red[tid + o]);
        __syncthreads();
    }
    m = red[0]; __syncthreads();

    float sum = 0.f;
    for (int t = tid; t <= s; t += blockDim.x) {
        float e = __expf(p[t] * scale - m);
        p[t] = e;
        sum += e;
    }
    red[tid] = sum; __syncthreads();
    for (int o = 128; o > 0; o >>= 1) {
        if (tid < o) red[tid] += red[tid + o];
        __syncthreads();
    }
    float inv = 1.f / red[0];
    const bf16 z = __float2bfloat16(0.f);
    for (int t = tid; t <= s; t += blockDim.x) {
        bf16 h, l; split1(p[t] * inv, h, l);
        ph[t] = h; pl[t] = l;
    }
    for (int t = s + 1 + tid; t < SEQ; t += blockDim.x) { ph[t] = z; pl[t] = z; }
}

// ---------------- HMMA GEMM: C[M,N] = A[M,K] @ B[N,K]^T ----------------
// A,B given as bf16 hi/lo pairs. 3-pass split product: Ah*Bh + Ah*Bl + Al*Bh.
// EPI: 0 none, 1 +=Cf, 2 relu(+bias), 3 +bias+Cf, 4 +bias
#define DEPTH     3
#define MAT_BYTES 10240          // 128 rows * 80B
#define STG_BYTES (4 * MAT_BYTES)
#define SMEM_TOT  (DEPTH * STG_BYTES)

template<int EPI, bool F32OUT, bool SPLITOUT>
__global__ __launch_bounds__(256, 1)
void mma_gemm(const bf16* __restrict__ Ah, const bf16* __restrict__ Al,
              const bf16* __restrict__ Bh, const bf16* __restrict__ Bl,
              float* __restrict__ Cf, bf16* __restrict__ Ch, bf16* __restrict__ Cl,
              const float* __restrict__ bias,
              int K, int lda, int ldb, int ldc,
              long bsA, long bsB, long bsC) {
    const int m0 = blockIdx.y << 7, n0 = blockIdx.x << 7;
    const long zA = (long)blockIdx.z * bsA;
    const long zB = (long)blockIdx.z * bsB;
    const long zC = (long)blockIdx.z * bsC;

    extern __shared__ char smem[];
    const uint32_t sbase = smem_u32(smem);
    const int tid = threadIdx.x;
    const int lane = tid & 31, wid = tid >> 5;
    const int wm = wid & 1, wn = wid >> 1;
    const int NK = K >> 5;

    const bf16* gm[4] = { Ah + zA + (long)m0 * lda, Al + zA + (long)m0 * lda,
                          Bh + zB + (long)n0 * ldb, Bl + zB + (long)n0 * ldb };
    const int row_lo = tid >> 2;     // 0..63
    const int atom   = tid & 3;

    float acc[4][4][4];
    #pragma unroll
    for (int a = 0; a < 4; a++)
        #pragma unroll
        for (int b = 0; b < 4; b++)
            #pragma unroll
            for (int c = 0; c < 4; c++) acc[a][b][c] = 0.f;

    // ---- pipelined loads ----
    #define LOAD_STAGE(kt, slot) do {                                          \
        uint32_t st_ = sbase + (slot) * STG_BYTES;                             \
        _Pragma("unroll")                                                      \
        for (int i = 0; i < 8; i++) {                                          \
            int mat = i >> 1;                                                  \
            int row = ((i & 1) << 6) + row_lo;                                 \
            int ld  = (mat < 2) ? lda : ldb;                                   \
            const bf16* g = gm[mat] + (long)row * ld + ((kt) << 5) + (atom << 3); \
            CP_ASYNC16(st_ + mat * MAT_BYTES + row * 80 + (atom << 4), g);     \
        }                                                                      \
        CP_COMMIT();                                                           \
    } while (0)

    LOAD_STAGE(0, 0);
    LOAD_STAGE(1, 1);

    for (int kt = 0; kt < NK; kt++) {
        CP_WAIT1();
        __syncthreads();
        if (kt + 2 < NK) { LOAD_STAGE(kt + 2, (kt + 2) % DEPTH); }
        else             { CP_COMMIT(); }

        uint32_t st = sbase + (kt % DEPTH) * STG_BYTES;
        #pragma unroll
        for (int s = 0; s < 2; s++) {
            uint32_t a_h[4][4], a_l[4][4], b_h[2][4], b_l[2][4];
            #pragma unroll
            for (int mt = 0; mt < 4; mt++) {
                uint32_t ad = st + (uint32_t)(wm * 64 + mt * 16 + (lane & 15)) * 80
                              + s * 32 + ((lane >> 4) << 4);
                LDSM_X4(a_h[mt], ad);
                LDSM_X4(a_l[mt], ad + MAT_BYTES);
            }
            #pragma unroll
            for (int p = 0; p < 2; p++) {
                uint32_t bd = st + 2 * MAT_BYTES
                              + (uint32_t)(wn * 32 + p * 16 + ((lane >> 4) << 3) + (lane & 7)) * 80
                              + s * 32 + (((lane >> 3) & 1) << 4);
                LDSM_X4(b_h[p], bd);
                LDSM_X4(b_l[p], bd + MAT_BYTES);
            }
            #pragma unroll
            for (int mt = 0; mt < 4; mt++)
                #pragma unroll
                for (int nt = 0; nt < 4; nt++) {
                    uint32_t bh0 = b_h[nt >> 1][(nt & 1) * 2];
                    uint32_t bh1 = b_h[nt >> 1][(nt & 1) * 2 + 1];
                    uint32_t bl0 = b_l[nt >> 1][(nt & 1) * 2];
                    uint32_t bl1 = b_l[nt >> 1][(nt & 1) * 2 + 1];
                    mma_bf16(acc[mt][nt], a_h[mt], bh0, bh1);
                    mma_bf16(acc[mt][nt], a_h[mt], bl0, bl1);
                    mma_bf16(acc[mt][nt], a_l[mt], bh0, bh1);
                }
        }
    }

    // ---- epilogue ----
    #pragma unroll
    for (int mt = 0; mt < 4; mt++) {
        #pragma unroll
        for (int nt = 0; nt < 4; nt++) {
            int mbase = m0 + wm * 64 + mt * 16 + (lane >> 2);
            int n = n0 + wn * 32 + nt * 8 + (lane & 3) * 2;
            #pragma unroll
            for (int hf = 0; hf < 2; hf++) {
                int mm = mbase + hf * 8;
                float vx = acc[mt][nt][hf * 2 + 0];
                float vy = acc[mt][nt][hf * 2 + 1];
                long idx = zC + (long)mm * ldc + n;
                if (EPI >= 2) { vx += bias[n]; vy += bias[n + 1]; }
                if (EPI == 2) { vx = fmaxf(vx, 0.f); vy = fmaxf(vy, 0.f); }
                if (EPI == 1 || EPI == 3) {
                    float2 old = *(const float2*)(Cf + idx);
                    vx += old.x; vy += old.y;
                }
                if (F32OUT) {
                    float2 o; o.x = vx; o.y = vy;
                    *(float2*)(Cf + idx) = o;
                }
                if (SPLITOUT) {
                    bf16 hx, lx, hy, ly;
                    split1(vx, hx, lx); split1(vy, hy, ly);
                    bf162 hv; hv.x = hx; hv.y = hy;
                    bf162 lv; lv.x = lx; lv.y = ly;
                    *(bf162*)(Ch + idx) = hv;
                    *(bf162*)(Cl + idx) = lv;
                }
            }
        }
    }
}

// ---------------- host ----------------
template<int EPI, bool F32O, bool SPL>
static void launch_mma(dim3 grid, const bf16* Ah, const bf16* Al,
                       const bf16* Bh, const bf16* Bl,
                       float* Cf, bf16* Ch, bf16* Cl, const float* bias,
                       int K, int lda, int ldb, int ldc,
                       long bsA = 0, long bsB = 0, long bsC = 0) {
    cudaFuncSetAttribute(mma_gemm<EPI, F32O, SPL>,
                         cudaFuncAttributeMaxDynamicSharedMemorySize, SMEM_TOT);
    mma_gemm<EPI, F32O, SPL><<<grid, 256, SMEM_TOT>>>(
        Ah, Al, Bh, Bl, Cf, Ch, Cl, bias, K, lda, ldb, ldc, bsA, bsB, bsC);
}

extern "C" void kernel_launch(void* const* d_in, const int* in_sizes, int n_in,
                              void* d_out, int out_size) {
    const int*   tokens    = (const int*)  d_in[0];
    const float* embedding = (const float*)d_in[1];
    const float* qkv_w     = (const float*)d_in[2];
    const float* o_w       = (const float*)d_in[3];
    const float* up_w      = (const float*)d_in[4];
    const float* up_b      = (const float*)d_in[5];
    const float* down_w    = (const float*)d_in[6];
    const float* down_b    = (const float*)d_in[7];
    const float* unemb_w   = (const float*)d_in[8];
    const float* unemb_b   = (const float*)d_in[9];
    float* logits = (float*)d_out;

    float *x, *qkv, *sc;
    bf16 *xh, *xl, *qh, *ql, *sh, *sl, *vTh, *vTl, *oh, *ol, *hh, *hl;
    bf16 *qkvTh, *qkvTl, *oTh, *oTl, *upTh, *upTl, *dnTh, *dnTl, *unTh, *unTl;
    cudaGetSymbolAddress((void**)&x, g_x);
    cudaGetSymbolAddress((void**)&qkv, g_qkv);
    cudaGetSymbolAddress((void**)&sc, g_scores);
    cudaGetSymbolAddress((void**)&xh, g_xh);   cudaGetSymbolAddress((void**)&xl, g_xl);
    cudaGetSymbolAddress((void**)&qh, g_qkvh); cudaGetSymbolAddress((void**)&ql, g_qkvl);
    cudaGetSymbolAddress((void**)&sh, g_sh);   cudaGetSymbolAddress((void**)&sl, g_sl);
    cudaGetSymbolAddress((void**)&vTh, g_vTh); cudaGetSymbolAddress((void**)&vTl, g_vTl);
    cudaGetSymbolAddress((void**)&oh, g_oh);   cudaGetSymbolAddress((void**)&ol, g_ol);
    cudaGetSymbolAddress((void**)&hh, g_hh);   cudaGetSymbolAddress((void**)&hl, g_hl);
    cudaGetSymbolAddress((void**)&qkvTh, g_qkvTh); cudaGetSymbolAddress((void**)&qkvTl, g_qkvTl);
    cudaGetSymbolAddress((void**)&oTh, g_oTh);     cudaGetSymbolAddress((void**)&oTl, g_oTl);
    cudaGetSymbolAddress((void**)&upTh, g_upTh);   cudaGetSymbolAddress((void**)&upTl, g_upTl);
    cudaGetSymbolAddress((void**)&dnTh, g_dnTh);   cudaGetSymbolAddress((void**)&dnTl, g_dnTl);
    cudaGetSymbolAddress((void**)&unTh, g_unTh);   cudaGetSymbolAddress((void**)&unTl, g_unTl);

    const float scale = 1.0f / sqrtf((float)KDIM);
    dim3 tb(32, 8);

    // weight transposes -> [N,K] bf16 hi/lo
    transpose_split<<<dim3(3 * KDIM / 32, HDIM / 32, LAYERS), tb>>>(
        qkv_w, qkvTh, qkvTl, HDIM, 3 * KDIM, (long)HDIM * 3 * KDIM, (long)HDIM * 3 * KDIM);
    transpose_split<<<dim3(HDIM / 32, KDIM / 32, LAYERS), tb>>>(
        o_w, oTh, oTl, KDIM, HDIM, (long)KDIM * HDIM, (long)KDIM * HDIM);
    transpose_split<<<dim3(IDIM / 32, HDIM / 32, LAYERS), tb>>>(
        up_w, upTh, upTl, HDIM, IDIM, (long)HDIM * IDIM, (long)HDIM * IDIM);
    transpose_split<<<dim3(HDIM / 32, IDIM / 32, LAYERS), tb>>>(
        down_w, dnTh, dnTl, IDIM, HDIM, (long)IDIM * HDIM, (long)IDIM * HDIM);
    transpose_split<<<dim3(VOCAB / 32, HDIM / 32, 1), tb>>>(
        unemb_w, unTh, unTl, HDIM, VOCAB, 0, 0);

    embed_split<<<MTOK, 256>>>(tokens, embedding, x, xh, xl);

    for (int l = 0; l < LAYERS; l++) {
        bf16* wqh = qkvTh + (long)l * 3 * KDIM * HDIM;
        bf16* wql = qkvTl + (long)l * 3 * KDIM * HDIM;
        bf16* woh = oTh   + (long)l * HDIM * KDIM;
        bf16* wol = oTl   + (long)l * HDIM * KDIM;
        bf16* wuh = upTh  + (long)l * IDIM * HDIM;
        bf16* wul = upTl  + (long)l * IDIM * HDIM;
        bf16* wdh = dnTh  + (long)l * HDIM * IDIM;
        bf16* wdl = dnTl  + (long)l * HDIM * IDIM;
        const float* bu = up_b   + (long)l * IDIM;
        const float* bd = down_b + (long)l * HDIM;

        // qkv = x @ Wqkv  -> fp32 (for V transpose) + split (Q,K operands)
        launch_mma<0, true, true>(dim3(3 * KDIM / 128, MTOK / 128, 1),
            xh, xl, wqh, wql, qkv, qh, ql, nullptr, HDIM, HDIM, HDIM, 3 * KDIM);

        // vT = V^T per batch (split)
        transpose_split<<<dim3(KDIM / 32, SEQ / 32, BATCH), tb>>>(
            qkv + 2 * KDIM, vTh, vTl, SEQ, 3 * KDIM,
            (long)SEQ * 3 * KDIM, (long)KDIM * SEQ);

        // scores = Q @ K^T per batch -> fp32
        launch_mma<0, true, false>(dim3(SEQ / 128, SEQ / 128, BATCH),
            qh, ql, qh + KDIM, ql + KDIM, sc, nullptr, nullptr, nullptr,
            KDIM, 3 * KDIM, 3 * KDIM, SEQ,
            (long)SEQ * 3 * KDIM, (long)SEQ * 3 * KDIM, (long)SEQ * SEQ);

        softmax_split<<<BATCH * SEQ, 256>>>(sc, sh, sl, scale);

        // o = attn @ V per batch -> split only
        launch_mma<0, false, true>(dim3(KDIM / 128, SEQ / 128, BATCH),
            sh, sl, vTh, vTl, nullptr, oh, ol, nullptr,
            SEQ, SEQ, SEQ, KDIM,
            (long)SEQ * SEQ, (long)KDIM * SEQ, (long)SEQ * KDIM);

        // x += o @ Wo -> fp32 + split
        launch_mma<1, true, true>(dim3(HDIM / 128, MTOK / 128, 1),
            oh, ol, woh, wol, x, xh, xl, nullptr, KDIM, KDIM, KDIM, HDIM);

        // h = relu(x @ Wu + bu) -> split only
        launch_mma<2, false, true>(dim3(IDIM / 128, MTOK / 128, 1),
            xh, xl, wuh, wul, nullptr, hh, hl, bu, HDIM, HDIM, HDIM, IDIM);

        // x += h @ Wd + bd -> fp32 + split
        launch_mma<3, true, true>(dim3(HDIM / 128, MTOK / 128, 1),
            hh, hl, wdh, wdl, x, xh, xl, bd, IDIM, IDIM, IDIM, HDIM);
    }

    // logits = x @ Wun + b -> fp32 only
    launch_mma<4, true, false>(dim3(VOCAB / 128, MTOK / 128, 1),
        xh, xl, unTh, unTl, logits, nullptr, nullptr, unemb_b,
        HDIM, HDIM, HDIM, VOCAB);
}